// round 3
// baseline (speedup 1.0000x reference)
#include <cuda_runtime.h>
#include <math.h>

// Problem constants (fixed by setup_inputs)
#define BATCH 2
#define S_TOT 21760
#define DIM 256
#define NHEAD 8
#define NLVL 4
#define NPT 4
#define DFF 1024
#define DHEAD 32
#define M_TOK (BATCH * S_TOT)   // 43520 rows

// ---------------------------------------------------------------------------
// Scratch (device globals — no runtime allocation allowed)
// ---------------------------------------------------------------------------
__device__ float g_q   [M_TOK * DIM];
__device__ float g_val [M_TOK * DIM];
__device__ float g_off [M_TOK * DIM];                 // NH*NL*NP*2 = 256/token
__device__ float g_attn[M_TOK * NHEAD * NLVL * NPT];  // 128/token
__device__ float g_acc [M_TOK * DIM];
__device__ float g_y   [M_TOK * DIM];
__device__ float g_x   [M_TOK * DIM];
__device__ float g_ffn [M_TOK * DFF];
__device__ float g_y2  [M_TOK * DIM];

// ---------------------------------------------------------------------------
// q = src + pos (vectorized)
// ---------------------------------------------------------------------------
__global__ void add4_kernel(const float4* __restrict__ a,
                            const float4* __restrict__ b,
                            float4* __restrict__ c, int n4) {
    int i = blockIdx.x * blockDim.x + threadIdx.x;
    if (i < n4) {
        float4 x = a[i], y = b[i];
        x.x += y.x; x.y += y.y; x.z += y.z; x.w += y.w;
        c[i] = x;
    }
}

// ---------------------------------------------------------------------------
// Tiled fp32 GEMM: C[M,N] = A[M,K] @ W[K,N] + bias (+ optional relu / residual)
// BM=BN=128, BK=8, 256 threads, 8x8 per thread.
// Requires M%128==0, N%128==0, K%8==0 (true for all calls here).
// fuse: 0 = none, 1 = relu, 2 = add residual res[M,N]
// ---------------------------------------------------------------------------
__global__ __launch_bounds__(256) void gemm128_kernel(
    const float* __restrict__ A, const float* __restrict__ W,
    const float* __restrict__ bias, const float* __restrict__ res,
    float* __restrict__ C, int M, int N, int K, int fuse)
{
    __shared__ float As[8][128];
    __shared__ float Bs[8][128];

    const int t  = threadIdx.x;
    const int tx = t & 15;       // N direction (16)
    const int ty = t >> 4;       // M direction (16)
    const int bm = blockIdx.y * 128;
    const int bn = blockIdx.x * 128;

    float acc[8][8];
#pragma unroll
    for (int i = 0; i < 8; i++)
#pragma unroll
        for (int j = 0; j < 8; j++) acc[i][j] = 0.f;

    const int ar = t >> 1;            // 0..127 (A tile row)
    const int ac = (t & 1) * 4;       // 0 or 4 (A tile col group)
    const int br = t >> 5;            // 0..7   (B tile row)
    const int bc = (t & 31) * 4;      // 0..124 (B tile col group)

    const float* Aptr = A + (size_t)(bm + ar) * K + ac;
    const float* Bptr = W + (size_t)br * N + bn + bc;

    for (int k0 = 0; k0 < K; k0 += 8) {
        float4 av = *(const float4*)(Aptr + k0);
        As[ac + 0][ar] = av.x;
        As[ac + 1][ar] = av.y;
        As[ac + 2][ar] = av.z;
        As[ac + 3][ar] = av.w;
        float4 bv = *(const float4*)(Bptr + (size_t)k0 * N);
        *(float4*)&Bs[br][bc] = bv;
        __syncthreads();

#pragma unroll
        for (int k = 0; k < 8; k++) {
            float4 a0 = *(const float4*)&As[k][ty * 8];
            float4 a1 = *(const float4*)&As[k][ty * 8 + 4];
            float4 b0 = *(const float4*)&Bs[k][tx * 8];
            float4 b1 = *(const float4*)&Bs[k][tx * 8 + 4];
            float ra[8] = {a0.x, a0.y, a0.z, a0.w, a1.x, a1.y, a1.z, a1.w};
            float rb[8] = {b0.x, b0.y, b0.z, b0.w, b1.x, b1.y, b1.z, b1.w};
#pragma unroll
            for (int i = 0; i < 8; i++)
#pragma unroll
                for (int j = 0; j < 8; j++)
                    acc[i][j] += ra[i] * rb[j];
        }
        __syncthreads();
    }

#pragma unroll
    for (int i = 0; i < 8; i++) {
        int r = bm + ty * 8 + i;
#pragma unroll
        for (int j = 0; j < 8; j += 4) {
            int c = bn + tx * 8 + j;
            float4 v;
            v.x = acc[i][j + 0] + bias[c + 0];
            v.y = acc[i][j + 1] + bias[c + 1];
            v.z = acc[i][j + 2] + bias[c + 2];
            v.w = acc[i][j + 3] + bias[c + 3];
            if (fuse == 1) {
                v.x = fmaxf(v.x, 0.f); v.y = fmaxf(v.y, 0.f);
                v.z = fmaxf(v.z, 0.f); v.w = fmaxf(v.w, 0.f);
            } else if (fuse == 2) {
                float4 rr = *(const float4*)&res[(size_t)r * N + c];
                v.x += rr.x; v.y += rr.y; v.z += rr.z; v.w += rr.w;
            }
            *(float4*)&C[(size_t)r * N + c] = v;
        }
    }
}

// ---------------------------------------------------------------------------
// Softmax over groups of 16 (NL*NP per head), in place. One thread per group.
// attn layout: [M_TOK][NH*16] with the 16 contiguous per head.
// ---------------------------------------------------------------------------
__global__ void softmax16_kernel(float* __restrict__ attn, int ngroups) {
    int i = blockIdx.x * blockDim.x + threadIdx.x;
    if (i >= ngroups) return;
    float* p = attn + (size_t)i * 16;
    float m = -1e30f;
#pragma unroll
    for (int j = 0; j < 16; j++) m = fmaxf(m, p[j]);
    float e[16], s = 0.f;
#pragma unroll
    for (int j = 0; j < 16; j++) { e[j] = expf(p[j] - m); s += e[j]; }
    float inv = 1.f / s;
#pragma unroll
    for (int j = 0; j < 16; j++) p[j] = e[j] * inv;
}

// ---------------------------------------------------------------------------
// Deformable sampling: one warp per (token, head); lane = channel (DH=32).
// acc[tok,h,:] = sum_{l,p} attn * bilinear(value_level_l, loc)
// ---------------------------------------------------------------------------
__global__ __launch_bounds__(256) void deform_sample_kernel(
    const float* __restrict__ value, const float* __restrict__ off,
    const float* __restrict__ attn, const float* __restrict__ refp,
    float* __restrict__ out)
{
    const int lane = threadIdx.x & 31;
    const int wid  = blockIdx.x * (blockDim.x >> 5) + (threadIdx.x >> 5);
    // wid in [0, M_TOK*NH)
    const int tok = wid >> 3;
    const int h   = wid & 7;
    const int b   = tok / S_TOT;

    // Per-(tok,h) offsets block: 32 contiguous floats (l,p,c). Lane loads one.
    float offv  = off[(size_t)tok * 256 + h * 32 + lane];
    float attnv = (lane < 16) ? attn[(size_t)tok * 128 + h * 16 + lane] : 0.f;
    float refv  = (lane < 8)  ? refp[(size_t)tok * 8 + lane] : 0.f;

    const float* vbase = value + (size_t)b * S_TOT * 256 + h * 32 + lane;

    const int   HW[4]     = {128, 64, 32, 16};
    const int   starts[4] = {0, 16384, 20480, 21504};

    float acc = 0.f;
#pragma unroll
    for (int l = 0; l < 4; l++) {
        const int   Hl = HW[l], Wl = HW[l];
        const float fH = (float)Hl, fW = (float)Wl;
        float rx = __shfl_sync(0xffffffffu, refv, 2 * l);
        float ry = __shfl_sync(0xffffffffu, refv, 2 * l + 1);
        const float* vlev = vbase + (size_t)starts[l] * 256;
#pragma unroll
        for (int p = 0; p < 4; p++) {
            int j = l * 4 + p;
            float ox = __shfl_sync(0xffffffffu, offv, 2 * j);
            float oy = __shfl_sync(0xffffffffu, offv, 2 * j + 1);
            float aw = __shfl_sync(0xffffffffu, attnv, j);

            float locx = rx + ox / fW;
            float locy = ry + oy / fH;
            float x = locx * fW - 0.5f;
            float y = locy * fH - 0.5f;
            float x0f = floorf(x), y0f = floorf(y);
            float wx = x - x0f, wy = y - y0f;
            int x0 = (int)x0f, y0 = (int)y0f;

            bool vx0 = (x0 >= 0) && (x0 < Wl);
            bool vx1 = (x0 + 1 >= 0) && (x0 + 1 < Wl);
            bool vy0 = (y0 >= 0) && (y0 < Hl);
            bool vy1 = (y0 + 1 >= 0) && (y0 + 1 < Hl);

            float samp = 0.f;
            if (vy0) {
                const float* rowp = vlev + (size_t)(y0 * Wl) * 256;
                if (vx0) samp += (1.f - wx) * (1.f - wy) * rowp[(size_t)x0 * 256];
                if (vx1) samp += wx * (1.f - wy) * rowp[(size_t)(x0 + 1) * 256];
            }
            if (vy1) {
                const float* rowp = vlev + (size_t)((y0 + 1) * Wl) * 256;
                if (vx0) samp += (1.f - wx) * wy * rowp[(size_t)x0 * 256];
                if (vx1) samp += wx * wy * rowp[(size_t)(x0 + 1) * 256];
            }
            acc += aw * samp;
        }
    }
    out[(size_t)tok * 256 + h * 32 + lane] = acc;
}

// ---------------------------------------------------------------------------
// LayerNorm over D=256: one warp per row, 8 elems/lane, two-pass.
// ---------------------------------------------------------------------------
__global__ __launch_bounds__(256) void ln_kernel(
    const float* __restrict__ in, const float* __restrict__ gamma,
    const float* __restrict__ beta, float* __restrict__ out, int rows)
{
    const int lane = threadIdx.x & 31;
    const int row  = blockIdx.x * 8 + (threadIdx.x >> 5);
    if (row >= rows) return;
    const float* p = in + (size_t)row * 256;

    float v[8];
    float s = 0.f;
#pragma unroll
    for (int i = 0; i < 8; i++) { v[i] = p[i * 32 + lane]; s += v[i]; }
#pragma unroll
    for (int o = 16; o > 0; o >>= 1) s += __shfl_xor_sync(0xffffffffu, s, o);
    float mu = s * (1.f / 256.f);

    float vs = 0.f;
#pragma unroll
    for (int i = 0; i < 8; i++) { float d = v[i] - mu; vs += d * d; }
#pragma unroll
    for (int o = 16; o > 0; o >>= 1) vs += __shfl_xor_sync(0xffffffffu, vs, o);
    float rstd = rsqrtf(vs * (1.f / 256.f) + 1e-5f);

    float* q = out + (size_t)row * 256;
#pragma unroll
    for (int i = 0; i < 8; i++) {
        int c = i * 32 + lane;
        q[c] = (v[i] - mu) * rstd * gamma[c] + beta[c];
    }
}

// ---------------------------------------------------------------------------
// Launch
// ---------------------------------------------------------------------------
extern "C" void kernel_launch(void* const* d_in, const int* in_sizes, int n_in,
                              void* d_out, int out_size) {
    const float* src    = (const float*)d_in[0];
    const float* pos    = (const float*)d_in[1];
    const float* refp   = (const float*)d_in[2];
    // d_in[3] spatial_shapes, d_in[4] level_start_index: fixed, hardcoded
    const float* W_off  = (const float*)d_in[5];
    const float* b_off  = (const float*)d_in[6];
    const float* W_attn = (const float*)d_in[7];
    const float* b_attn = (const float*)d_in[8];
    const float* W_val  = (const float*)d_in[9];
    const float* b_val  = (const float*)d_in[10];
    const float* W_out  = (const float*)d_in[11];
    const float* b_out  = (const float*)d_in[12];
    const float* W_f1   = (const float*)d_in[13];
    const float* b_f1   = (const float*)d_in[14];
    const float* W_f2   = (const float*)d_in[15];
    const float* b_f2   = (const float*)d_in[16];
    const float* ln1g   = (const float*)d_in[17];
    const float* ln1b   = (const float*)d_in[18];
    const float* ln2g   = (const float*)d_in[19];
    const float* ln2b   = (const float*)d_in[20];
    float* out = (float*)d_out;

    float *q, *val, *off, *attn, *acc, *y, *x, *ffn, *y2;
    cudaGetSymbolAddress((void**)&q,    g_q);
    cudaGetSymbolAddress((void**)&val,  g_val);
    cudaGetSymbolAddress((void**)&off,  g_off);
    cudaGetSymbolAddress((void**)&attn, g_attn);
    cudaGetSymbolAddress((void**)&acc,  g_acc);
    cudaGetSymbolAddress((void**)&y,    g_y);
    cudaGetSymbolAddress((void**)&x,    g_x);
    cudaGetSymbolAddress((void**)&ffn,  g_ffn);
    cudaGetSymbolAddress((void**)&y2,   g_y2);

    // 1. q = src + pos
    int n4 = M_TOK * DIM / 4;
    add4_kernel<<<(n4 + 255) / 256, 256>>>((const float4*)src, (const float4*)pos,
                                           (float4*)q, n4);

    dim3 grid256(DIM / 128, M_TOK / 128);   // (2, 340)
    dim3 grid128(1, M_TOK / 128);           // attn proj, N=128
    dim3 gridFFN(DFF / 128, M_TOK / 128);   // (8, 340)

    // 2. value = src @ W_val + b_val
    gemm128_kernel<<<grid256, 256>>>(src, W_val, b_val, nullptr, val,
                                     M_TOK, DIM, DIM, 0);
    // 3. off = q @ W_off + b_off
    gemm128_kernel<<<grid256, 256>>>(q, W_off, b_off, nullptr, off,
                                     M_TOK, 256, DIM, 0);
    // 4. attn logits = q @ W_attn + b_attn
    gemm128_kernel<<<grid128, 256>>>(q, W_attn, b_attn, nullptr, attn,
                                     M_TOK, 128, DIM, 0);
    // 5. softmax over 16 per (tok, head)
    int ngroups = M_TOK * NHEAD;
    softmax16_kernel<<<(ngroups + 255) / 256, 256>>>(attn, ngroups);

    // 6. deformable sampling -> acc
    deform_sample_kernel<<<M_TOK * NHEAD / 8, 256>>>(val, off, attn, refp, acc);

    // 7. y = acc @ W_out + b_out + src
    gemm128_kernel<<<grid256, 256>>>(acc, W_out, b_out, src, y,
                                     M_TOK, DIM, DIM, 2);
    // 8. x = LN1(y)
    ln_kernel<<<M_TOK / 8, 256>>>(y, ln1g, ln1b, x, M_TOK);

    // 9. ffn = relu(x @ W_f1 + b_f1)
    gemm128_kernel<<<gridFFN, 256>>>(x, W_f1, b_f1, nullptr, ffn,
                                     M_TOK, DFF, DIM, 1);
    // 10. y2 = ffn @ W_f2 + b_f2 + x
    gemm128_kernel<<<grid256, 256>>>(ffn, W_f2, b_f2, x, y2,
                                     M_TOK, DIM, DFF, 2);
    // 11. out = LN2(y2)
    ln_kernel<<<M_TOK / 8, 256>>>(y2, ln2g, ln2b, out, M_TOK);
}

// round 6
// speedup vs baseline: 1.9498x; 1.9498x over previous
#include <cuda_runtime.h>
#include <stdint.h>
#include <math.h>

// Problem constants (fixed by setup_inputs)
#define BATCH 2
#define S_TOT 21760
#define DIM 256
#define NHEAD 8
#define NLVL 4
#define NPT 4
#define DFF 1024
#define DHEAD 32
#define M_TOK (BATCH * S_TOT)   // 43520 rows

// ---------------------------------------------------------------------------
// Scratch (device globals — no runtime allocation allowed)
// ---------------------------------------------------------------------------
__device__ float g_q   [M_TOK * DIM];
__device__ float g_val [M_TOK * DIM];
__device__ float g_off [M_TOK * DIM];
__device__ float g_attn[M_TOK * NHEAD * NLVL * NPT];
__device__ float g_acc [M_TOK * DIM];
__device__ float g_y   [M_TOK * DIM];
__device__ float g_x   [M_TOK * DIM];
__device__ float g_ffn [M_TOK * DFF];
__device__ float g_y2  [M_TOK * DIM];

// Transposed (K-major) weights: WT[n*K + k] = W[k*N + n]
__device__ float g_WT_val [DIM * DIM];
__device__ float g_WT_off [DIM * DIM];
__device__ float g_WT_attn[128 * DIM];
__device__ float g_WT_out [DIM * DIM];
__device__ float g_WT_f1  [DFF * DIM];
__device__ float g_WT_f2  [DIM * DFF];

// ---------------------------------------------------------------------------
// Weight transpose: WT[n*K + k] = W[k*N + n]. K, N multiples of 32.
// ---------------------------------------------------------------------------
__global__ void transpose_kernel(const float* __restrict__ W,
                                 float* __restrict__ WT, int K, int N) {
    __shared__ float tile[32][33];
    int bn = blockIdx.x * 32;
    int bk = blockIdx.y * 32;
    int tx = threadIdx.x, ty0 = threadIdx.y;
#pragma unroll
    for (int i = 0; i < 4; i++) {
        int ty = ty0 + i * 8;
        tile[ty][tx] = W[(size_t)(bk + ty) * N + bn + tx];
    }
    __syncthreads();
#pragma unroll
    for (int i = 0; i < 4; i++) {
        int ty = ty0 + i * 8;
        WT[(size_t)(bn + ty) * K + bk + tx] = tile[tx][ty];
    }
}

// ---------------------------------------------------------------------------
// tf32 mma.sync GEMM: C[M,N] = A[M,K] @ WT[N,K]^T + bias (+relu / +res)
// BM=BN=128, BK=16, 256 threads (8 warps, 2x4), warp tile 64x32.
// Double-buffered smem with register prefetch. fuse: 0 none, 1 relu, 2 res.
// ---------------------------------------------------------------------------
#define BK 16
#define SMS 20   // smem row stride (floats): conflict-free for frag patterns

__device__ __forceinline__ uint32_t f2tf32(float f) {
    uint32_t u;
    asm("cvt.rna.tf32.f32 %0, %1;" : "=r"(u) : "f"(f));
    return u;
}

__global__ __launch_bounds__(256) void gemm_tc_kernel(
    const float* __restrict__ A, const float* __restrict__ WT,
    const float* __restrict__ bias, const float* __restrict__ res,
    float* __restrict__ C, int M, int N, int K, int fuse)
{
    __shared__ uint32_t sA[2][128 * SMS];
    __shared__ uint32_t sB[2][128 * SMS];

    const int t    = threadIdx.x;
    const int wid  = t >> 5;
    const int lane = t & 31;
    const int wm   = (wid >> 2) * 64;   // warp M offset (0 or 64)
    const int wn   = (wid & 3) * 32;    // warp N offset (0,32,64,96)
    const int bm   = blockIdx.y * 128;
    const int bn   = blockIdx.x * 128;

    // staging decomposition: 512 float4 per tile, 2 per thread
    const int f0   = t;          // float4 index pass 0
    const int f1   = t + 256;    // pass 1
    const int r0   = f0 >> 2, k0g = (f0 & 3) << 2;
    const int r1   = f1 >> 2, k1g = (f1 & 3) << 2;

    const float* Ab = A  + (size_t)bm * K;
    const float* Bb = WT + (size_t)bn * K;

    float acc[4][4][4];
#pragma unroll
    for (int i = 0; i < 4; i++)
#pragma unroll
        for (int j = 0; j < 4; j++)
#pragma unroll
            for (int e = 0; e < 4; e++) acc[i][j][e] = 0.f;

    const int nch = K >> 4;

    // prefetch registers
    float4 pa0, pa1, pb0, pb1;

    auto ldg = [&](int c) {
        const int kb = c << 4;
        pa0 = *(const float4*)(Ab + (size_t)r0 * K + kb + k0g);
        pa1 = *(const float4*)(Ab + (size_t)r1 * K + kb + k1g);
        pb0 = *(const float4*)(Bb + (size_t)r0 * K + kb + k0g);
        pb1 = *(const float4*)(Bb + (size_t)r1 * K + kb + k1g);
    };
    auto sts = [&](int b) {
        uint32_t* a = sA[b];
        uint32_t* bp = sB[b];
        uint4 v;
        v.x = f2tf32(pa0.x); v.y = f2tf32(pa0.y); v.z = f2tf32(pa0.z); v.w = f2tf32(pa0.w);
        *(uint4*)&a[r0 * SMS + k0g] = v;
        v.x = f2tf32(pa1.x); v.y = f2tf32(pa1.y); v.z = f2tf32(pa1.z); v.w = f2tf32(pa1.w);
        *(uint4*)&a[r1 * SMS + k1g] = v;
        v.x = f2tf32(pb0.x); v.y = f2tf32(pb0.y); v.z = f2tf32(pb0.z); v.w = f2tf32(pb0.w);
        *(uint4*)&bp[r0 * SMS + k0g] = v;
        v.x = f2tf32(pb1.x); v.y = f2tf32(pb1.y); v.z = f2tf32(pb1.z); v.w = f2tf32(pb1.w);
        *(uint4*)&bp[r1 * SMS + k1g] = v;
    };

    const int lr = lane >> 2;   // 0..7
    const int lk = lane & 3;    // 0..3

    auto compute = [&](int b) {
        const uint32_t* a = sA[b];
        const uint32_t* bp = sB[b];
#pragma unroll
        for (int ks = 0; ks < BK; ks += 8) {
            uint32_t af[4][4], bf[4][2];
#pragma unroll
            for (int mt = 0; mt < 4; mt++) {
                int mr = wm + mt * 16 + lr;
                af[mt][0] = a[mr * SMS + ks + lk];
                af[mt][1] = a[(mr + 8) * SMS + ks + lk];
                af[mt][2] = a[mr * SMS + ks + lk + 4];
                af[mt][3] = a[(mr + 8) * SMS + ks + lk + 4];
            }
#pragma unroll
            for (int nt = 0; nt < 4; nt++) {
                int nc = wn + nt * 8 + lr;
                bf[nt][0] = bp[nc * SMS + ks + lk];
                bf[nt][1] = bp[nc * SMS + ks + lk + 4];
            }
#pragma unroll
            for (int mt = 0; mt < 4; mt++)
#pragma unroll
                for (int nt = 0; nt < 4; nt++) {
                    asm volatile(
                        "mma.sync.aligned.m16n8k8.row.col.f32.tf32.tf32.f32 "
                        "{%0,%1,%2,%3}, {%4,%5,%6,%7}, {%8,%9}, {%0,%1,%2,%3};"
                        : "+f"(acc[mt][nt][0]), "+f"(acc[mt][nt][1]),
                          "+f"(acc[mt][nt][2]), "+f"(acc[mt][nt][3])
                        : "r"(af[mt][0]), "r"(af[mt][1]),
                          "r"(af[mt][2]), "r"(af[mt][3]),
                          "r"(bf[nt][0]), "r"(bf[nt][1]));
                }
        }
    };

    ldg(0);
    sts(0);
    __syncthreads();

    for (int c = 0; c < nch; c++) {
        if (c + 1 < nch) ldg(c + 1);
        compute(c & 1);
        if (c + 1 < nch) {
            sts((c + 1) & 1);
            __syncthreads();
        }
    }

    // ---- epilogue ----
    const int cL = (lane & 3) * 2;
#pragma unroll
    for (int mt = 0; mt < 4; mt++) {
        int row = bm + wm + mt * 16 + lr;
#pragma unroll
        for (int nt = 0; nt < 4; nt++) {
            int col = bn + wn + nt * 8 + cL;
            float2 v0, v1;
            v0.x = acc[mt][nt][0] + bias[col];
            v0.y = acc[mt][nt][1] + bias[col + 1];
            v1.x = acc[mt][nt][2] + bias[col];
            v1.y = acc[mt][nt][3] + bias[col + 1];
            if (fuse == 1) {
                v0.x = fmaxf(v0.x, 0.f); v0.y = fmaxf(v0.y, 0.f);
                v1.x = fmaxf(v1.x, 0.f); v1.y = fmaxf(v1.y, 0.f);
            } else if (fuse == 2) {
                float2 r0v = *(const float2*)&res[(size_t)row * N + col];
                float2 r1v = *(const float2*)&res[(size_t)(row + 8) * N + col];
                v0.x += r0v.x; v0.y += r0v.y;
                v1.x += r1v.x; v1.y += r1v.y;
            }
            *(float2*)&C[(size_t)row * N + col] = v0;
            *(float2*)&C[(size_t)(row + 8) * N + col] = v1;
        }
    }
}

// ---------------------------------------------------------------------------
// q = src + pos
// ---------------------------------------------------------------------------
__global__ void add4_kernel(const float4* __restrict__ a,
                            const float4* __restrict__ b,
                            float4* __restrict__ c, int n4) {
    int i = blockIdx.x * blockDim.x + threadIdx.x;
    if (i < n4) {
        float4 x = a[i], y = b[i];
        x.x += y.x; x.y += y.y; x.z += y.z; x.w += y.w;
        c[i] = x;
    }
}

// ---------------------------------------------------------------------------
// Softmax over groups of 16, in place. One thread per (tok, head).
// ---------------------------------------------------------------------------
__global__ void softmax16_kernel(float* __restrict__ attn, int ngroups) {
    int i = blockIdx.x * blockDim.x + threadIdx.x;
    if (i >= ngroups) return;
    float* p = attn + (size_t)i * 16;
    float m = -1e30f;
#pragma unroll
    for (int j = 0; j < 16; j++) m = fmaxf(m, p[j]);
    float e[16], s = 0.f;
#pragma unroll
    for (int j = 0; j < 16; j++) { e[j] = expf(p[j] - m); s += e[j]; }
    float inv = 1.f / s;
#pragma unroll
    for (int j = 0; j < 16; j++) p[j] = e[j] * inv;
}

// ---------------------------------------------------------------------------
// Deformable sampling: one warp per (token, head); lane = channel (DH=32).
// ---------------------------------------------------------------------------
__global__ __launch_bounds__(256) void deform_sample_kernel(
    const float* __restrict__ value, const float* __restrict__ off,
    const float* __restrict__ attn, const float* __restrict__ refp,
    float* __restrict__ out)
{
    const int lane = threadIdx.x & 31;
    const int wid  = blockIdx.x * (blockDim.x >> 5) + (threadIdx.x >> 5);
    const int tok = wid >> 3;
    const int h   = wid & 7;
    const int b   = tok / S_TOT;

    float offv  = off[(size_t)tok * 256 + h * 32 + lane];
    float attnv = (lane < 16) ? attn[(size_t)tok * 128 + h * 16 + lane] : 0.f;
    float refv  = (lane < 8)  ? refp[(size_t)tok * 8 + lane] : 0.f;

    const float* vbase = value + (size_t)b * S_TOT * 256 + h * 32 + lane;

    const int HW[4]     = {128, 64, 32, 16};
    const int starts[4] = {0, 16384, 20480, 21504};

    float acc = 0.f;
#pragma unroll
    for (int l = 0; l < 4; l++) {
        const int   Hl = HW[l], Wl = HW[l];
        const float fH = (float)Hl, fW = (float)Wl;
        float rx = __shfl_sync(0xffffffffu, refv, 2 * l);
        float ry = __shfl_sync(0xffffffffu, refv, 2 * l + 1);
        const float* vlev = vbase + (size_t)starts[l] * 256;
#pragma unroll
        for (int p = 0; p < 4; p++) {
            int j = l * 4 + p;
            float ox = __shfl_sync(0xffffffffu, offv, 2 * j);
            float oy = __shfl_sync(0xffffffffu, offv, 2 * j + 1);
            float aw = __shfl_sync(0xffffffffu, attnv, j);

            float locx = rx + ox / fW;
            float locy = ry + oy / fH;
            float x = locx * fW - 0.5f;
            float y = locy * fH - 0.5f;
            float x0f = floorf(x), y0f = floorf(y);
            float wx = x - x0f, wy = y - y0f;
            int x0 = (int)x0f, y0 = (int)y0f;

            bool vx0 = (x0 >= 0) && (x0 < Wl);
            bool vx1 = (x0 + 1 >= 0) && (x0 + 1 < Wl);
            bool vy0 = (y0 >= 0) && (y0 < Hl);
            bool vy1 = (y0 + 1 >= 0) && (y0 + 1 < Hl);

            float samp = 0.f;
            if (vy0) {
                const float* rowp = vlev + (size_t)(y0 * Wl) * 256;
                if (vx0) samp += (1.f - wx) * (1.f - wy) * rowp[(size_t)x0 * 256];
                if (vx1) samp += wx * (1.f - wy) * rowp[(size_t)(x0 + 1) * 256];
            }
            if (vy1) {
                const float* rowp = vlev + (size_t)((y0 + 1) * Wl) * 256;
                if (vx0) samp += (1.f - wx) * wy * rowp[(size_t)x0 * 256];
                if (vx1) samp += wx * wy * rowp[(size_t)(x0 + 1) * 256];
            }
            acc += aw * samp;
        }
    }
    out[(size_t)tok * 256 + h * 32 + lane] = acc;
}

// ---------------------------------------------------------------------------
// LayerNorm over D=256: one warp per row.
// ---------------------------------------------------------------------------
__global__ __launch_bounds__(256) void ln_kernel(
    const float* __restrict__ in, const float* __restrict__ gamma,
    const float* __restrict__ beta, float* __restrict__ out, int rows)
{
    const int lane = threadIdx.x & 31;
    const int row  = blockIdx.x * 8 + (threadIdx.x >> 5);
    if (row >= rows) return;
    const float* p = in + (size_t)row * 256;

    float v[8];
    float s = 0.f;
#pragma unroll
    for (int i = 0; i < 8; i++) { v[i] = p[i * 32 + lane]; s += v[i]; }
#pragma unroll
    for (int o = 16; o > 0; o >>= 1) s += __shfl_xor_sync(0xffffffffu, s, o);
    float mu = s * (1.f / 256.f);

    float vs = 0.f;
#pragma unroll
    for (int i = 0; i < 8; i++) { float d = v[i] - mu; vs += d * d; }
#pragma unroll
    for (int o = 16; o > 0; o >>= 1) vs += __shfl_xor_sync(0xffffffffu, vs, o);
    float rstd = rsqrtf(vs * (1.f / 256.f) + 1e-5f);

    float* q = out + (size_t)row * 256;
#pragma unroll
    for (int i = 0; i < 8; i++) {
        int c = i * 32 + lane;
        q[c] = (v[i] - mu) * rstd * gamma[c] + beta[c];
    }
}

// ---------------------------------------------------------------------------
// Launch
// ---------------------------------------------------------------------------
extern "C" void kernel_launch(void* const* d_in, const int* in_sizes, int n_in,
                              void* d_out, int out_size) {
    const float* src    = (const float*)d_in[0];
    const float* pos    = (const float*)d_in[1];
    const float* refp   = (const float*)d_in[2];
    const float* W_off  = (const float*)d_in[5];
    const float* b_off  = (const float*)d_in[6];
    const float* W_attn = (const float*)d_in[7];
    const float* b_attn = (const float*)d_in[8];
    const float* W_val  = (const float*)d_in[9];
    const float* b_val  = (const float*)d_in[10];
    const float* W_out  = (const float*)d_in[11];
    const float* b_out  = (const float*)d_in[12];
    const float* W_f1   = (const float*)d_in[13];
    const float* b_f1   = (const float*)d_in[14];
    const float* W_f2   = (const float*)d_in[15];
    const float* b_f2   = (const float*)d_in[16];
    const float* ln1g   = (const float*)d_in[17];
    const float* ln1b   = (const float*)d_in[18];
    const float* ln2g   = (const float*)d_in[19];
    const float* ln2b   = (const float*)d_in[20];
    float* out = (float*)d_out;

    float *q, *val, *off, *attn, *acc, *y, *x, *ffn, *y2;
    float *wtv, *wto, *wta, *wtu, *wt1, *wt2;
    cudaGetSymbolAddress((void**)&q,    g_q);
    cudaGetSymbolAddress((void**)&val,  g_val);
    cudaGetSymbolAddress((void**)&off,  g_off);
    cudaGetSymbolAddress((void**)&attn, g_attn);
    cudaGetSymbolAddress((void**)&acc,  g_acc);
    cudaGetSymbolAddress((void**)&y,    g_y);
    cudaGetSymbolAddress((void**)&x,    g_x);
    cudaGetSymbolAddress((void**)&ffn,  g_ffn);
    cudaGetSymbolAddress((void**)&y2,   g_y2);
    cudaGetSymbolAddress((void**)&wtv,  g_WT_val);
    cudaGetSymbolAddress((void**)&wto,  g_WT_off);
    cudaGetSymbolAddress((void**)&wta,  g_WT_attn);
    cudaGetSymbolAddress((void**)&wtu,  g_WT_out);
    cudaGetSymbolAddress((void**)&wt1,  g_WT_f1);
    cudaGetSymbolAddress((void**)&wt2,  g_WT_f2);

    dim3 tb(32, 8);
    // Transpose all weights to K-major
    transpose_kernel<<<dim3(DIM / 32,  DIM / 32),  tb>>>(W_val,  wtv, DIM, DIM);
    transpose_kernel<<<dim3(DIM / 32,  DIM / 32),  tb>>>(W_off,  wto, DIM, DIM);
    transpose_kernel<<<dim3(128 / 32,  DIM / 32),  tb>>>(W_attn, wta, DIM, 128);
    transpose_kernel<<<dim3(DIM / 32,  DIM / 32),  tb>>>(W_out,  wtu, DIM, DIM);
    transpose_kernel<<<dim3(DFF / 32,  DIM / 32),  tb>>>(W_f1,   wt1, DIM, DFF);
    transpose_kernel<<<dim3(DIM / 32,  DFF / 32),  tb>>>(W_f2,   wt2, DFF, DIM);

    // 1. q = src + pos
    int n4 = M_TOK * DIM / 4;
    add4_kernel<<<(n4 + 255) / 256, 256>>>((const float4*)src, (const float4*)pos,
                                           (float4*)q, n4);

    dim3 grid256(DIM / 128, M_TOK / 128);   // (2, 340)
    dim3 grid128(1, M_TOK / 128);           // (1, 340)
    dim3 gridFFN(DFF / 128, M_TOK / 128);   // (8, 340)

    // 2. value = src @ W_val + b_val
    gemm_tc_kernel<<<grid256, 256>>>(src, wtv, b_val, nullptr, val,
                                     M_TOK, DIM, DIM, 0);
    // 3. off = q @ W_off + b_off
    gemm_tc_kernel<<<grid256, 256>>>(q, wto, b_off, nullptr, off,
                                     M_TOK, 256, DIM, 0);
    // 4. attn logits = q @ W_attn + b_attn
    gemm_tc_kernel<<<grid128, 256>>>(q, wta, b_attn, nullptr, attn,
                                     M_TOK, 128, DIM, 0);
    // 5. softmax over 16 per (tok, head)
    int ngroups = M_TOK * NHEAD;
    softmax16_kernel<<<(ngroups + 255) / 256, 256>>>(attn, ngroups);

    // 6. deformable sampling -> acc
    deform_sample_kernel<<<M_TOK * NHEAD / 8, 256>>>(val, off, attn, refp, acc);

    // 7. y = acc @ W_out + b_out + src
    gemm_tc_kernel<<<grid256, 256>>>(acc, wtu, b_out, src, y,
                                     M_TOK, DIM, DIM, 2);
    // 8. x = LN1(y)
    ln_kernel<<<M_TOK / 8, 256>>>(y, ln1g, ln1b, x, M_TOK);

    // 9. ffn = relu(x @ W_f1 + b_f1)
    gemm_tc_kernel<<<gridFFN, 256>>>(x, wt1, b_f1, nullptr, ffn,
                                     M_TOK, DFF, DIM, 1);
    // 10. y2 = ffn @ W_f2 + b_f2 + x
    gemm_tc_kernel<<<grid256, 256>>>(ffn, wt2, b_f2, x, y2,
                                     M_TOK, DIM, DFF, 2);
    // 11. out = LN2(y2)
    ln_kernel<<<M_TOK / 8, 256>>>(y2, ln2g, ln2b, out, M_TOK);
}

// round 7
// speedup vs baseline: 2.0438x; 1.0482x over previous
#include <cuda_runtime.h>
#include <stdint.h>
#include <math.h>

// Problem constants (fixed by setup_inputs)
#define BATCH 2
#define S_TOT 21760
#define DIM 256
#define NHEAD 8
#define NLVL 4
#define NPT 4
#define DFF 1024
#define DHEAD 32
#define M_TOK (BATCH * S_TOT)   // 43520 rows

// ---------------------------------------------------------------------------
// Scratch (device globals — no runtime allocation allowed)
// ---------------------------------------------------------------------------
__device__ float g_q     [M_TOK * DIM];
__device__ float g_val   [M_TOK * DIM];
__device__ float g_oa    [M_TOK * 384];   // merged offsets(256) + attn logits(128)
__device__ float g_acc   [M_TOK * DIM];
__device__ float g_y     [M_TOK * DIM];
__device__ float g_x     [M_TOK * DIM];
__device__ float g_ffn   [M_TOK * DFF];
__device__ float g_y2    [M_TOK * DIM];

// Transposed (K-major), tf32-pre-rounded weights: WT[n*K + k] = tf32(W[k*N + n])
__device__ float g_WT_val [DIM * DIM];
__device__ float g_WT_oa  [384 * DIM];    // rows 0..255 = W_off cols, 256..383 = W_attn cols
__device__ float g_WT_out [DIM * DIM];
__device__ float g_WT_f1  [DFF * DIM];
__device__ float g_WT_f2  [DIM * DFF];
__device__ float g_b_oa   [384];          // concat(b_off, b_attn)

__device__ __forceinline__ uint32_t f2tf32(float f) {
    uint32_t u;
    asm("cvt.rna.tf32.f32 %0, %1;" : "=r"(u) : "f"(f));
    return u;
}

__device__ __forceinline__ uint32_t smem_u32(const void* p) {
    uint32_t a;
    asm("{ .reg .u64 t; cvta.to.shared.u64 t, %1; cvt.u32.u64 %0, t; }"
        : "=r"(a) : "l"(p));
    return a;
}

// ---------------------------------------------------------------------------
// One launch: all weight transposes (with tf32 pre-round) + bias concat.
// 32x32 tiles, 32x8 threads. Block mapping table below.
// ---------------------------------------------------------------------------
__global__ void transpose_all_kernel(
    const float* __restrict__ W_val, const float* __restrict__ W_off,
    const float* __restrict__ W_attn, const float* __restrict__ W_out,
    const float* __restrict__ W_f1,  const float* __restrict__ W_f2,
    const float* __restrict__ b_off, const float* __restrict__ b_attn)
{
    const int bid = blockIdx.x;
    const int tx = threadIdx.x, ty0 = threadIdx.y;

    if (bid >= 736) {   // bias concat blocks (736, 737)
        int idx = (bid - 736) * 256 + ty0 * 32 + tx;
        if (idx < 384)
            g_b_oa[idx] = (idx < 256) ? b_off[idx] : b_attn[idx - 256];
        return;
    }

    const float* W; float* WT; int K, N, lt;
    if      (bid < 64)  { W = W_val;  WT = g_WT_val;            K = 256;  N = 256;  lt = bid; }
    else if (bid < 128) { W = W_off;  WT = g_WT_oa;             K = 256;  N = 256;  lt = bid - 64; }
    else if (bid < 160) { W = W_attn; WT = g_WT_oa + 256 * 256; K = 256;  N = 128;  lt = bid - 128; }
    else if (bid < 224) { W = W_out;  WT = g_WT_out;            K = 256;  N = 256;  lt = bid - 160; }
    else if (bid < 480) { W = W_f1;   WT = g_WT_f1;             K = 256;  N = 1024; lt = bid - 224; }
    else                { W = W_f2;   WT = g_WT_f2;             K = 1024; N = 256;  lt = bid - 480; }

    const int tiles_x = N >> 5;
    const int bn = (lt % tiles_x) * 32;
    const int bk = (lt / tiles_x) * 32;

    __shared__ float tile[32][33];
#pragma unroll
    for (int i = 0; i < 4; i++) {
        int ty = ty0 + i * 8;
        tile[ty][tx] = W[(size_t)(bk + ty) * N + bn + tx];
    }
    __syncthreads();
#pragma unroll
    for (int i = 0; i < 4; i++) {
        int ty = ty0 + i * 8;
        WT[(size_t)(bn + ty) * K + bk + tx] =
            __uint_as_float(f2tf32(tile[tx][ty]));
    }
}

// ---------------------------------------------------------------------------
// tf32 mma.sync GEMM with cp.async 3-stage pipeline.
// C[M,N] = A[M,K] @ WT[N,K]^T + bias (+relu / +res)
// BM=BN=128, BK=16, 256 threads (8 warps, 2x4), warp tile 64x32.
// WT pre-rounded to tf32; A rounded at fragment load.
// fuse: 0 none, 1 relu, 2 residual add
// ---------------------------------------------------------------------------
#define BKC 16
#define SMS 20   // smem row stride (floats): conflict-free for frag patterns
#define STG 3
#define BUF (128 * SMS)

__global__ __launch_bounds__(256) void gemm_tc_kernel(
    const float* __restrict__ A, const float* __restrict__ WT,
    const float* __restrict__ bias, const float* __restrict__ res,
    float* __restrict__ C, int M, int N, int K, int fuse)
{
    extern __shared__ float smem[];
    float* sA = smem;               // STG * BUF floats
    float* sB = smem + STG * BUF;   // STG * BUF floats

    const int t    = threadIdx.x;
    const int wid  = t >> 5;
    const int lane = t & 31;
    const int wm   = (wid >> 2) * 64;
    const int wn   = (wid & 3) * 32;
    const int bm   = blockIdx.y * 128;
    const int bn   = blockIdx.x * 128;

    // copy units: 512 x 16B per operand tile; thread t does units t and t+256
    const int r0 = t >> 2,         s0 = (t & 3) << 2;
    const int r1 = (t + 256) >> 2, s1 = ((t + 256) & 3) << 2;

    const float* Ab = A  + (size_t)bm * K;
    const float* Bb = WT + (size_t)bn * K;

    float acc[4][4][4];
#pragma unroll
    for (int i = 0; i < 4; i++)
#pragma unroll
        for (int j = 0; j < 4; j++)
#pragma unroll
            for (int e = 0; e < 4; e++) acc[i][j][e] = 0.f;

    const int nch = K >> 4;

    auto issue = [&](int c) {
        const int s = c % STG;
        float* a = sA + s * BUF;
        float* b = sB + s * BUF;
        const int kb = c << 4;
        uint32_t d;
        d = smem_u32(a + r0 * SMS + s0);
        asm volatile("cp.async.ca.shared.global [%0], [%1], 16;"
                     :: "r"(d), "l"(Ab + (size_t)r0 * K + kb + s0) : "memory");
        d = smem_u32(a + r1 * SMS + s1);
        asm volatile("cp.async.ca.shared.global [%0], [%1], 16;"
                     :: "r"(d), "l"(Ab + (size_t)r1 * K + kb + s1) : "memory");
        d = smem_u32(b + r0 * SMS + s0);
        asm volatile("cp.async.ca.shared.global [%0], [%1], 16;"
                     :: "r"(d), "l"(Bb + (size_t)r0 * K + kb + s0) : "memory");
        d = smem_u32(b + r1 * SMS + s1);
        asm volatile("cp.async.ca.shared.global [%0], [%1], 16;"
                     :: "r"(d), "l"(Bb + (size_t)r1 * K + kb + s1) : "memory");
        asm volatile("cp.async.commit_group;" ::: "memory");
    };

    const int lr = lane >> 2;   // 0..7
    const int lk = lane & 3;    // 0..3

    auto compute = [&](int c) {
        const int s = c % STG;
        const float* a  = sA + s * BUF;
        const float* bp = sB + s * BUF;
#pragma unroll
        for (int ks = 0; ks < BKC; ks += 8) {
            uint32_t af[4][4], bf[4][2];
#pragma unroll
            for (int mt = 0; mt < 4; mt++) {
                int mr = wm + mt * 16 + lr;
                af[mt][0] = f2tf32(a[mr * SMS + ks + lk]);
                af[mt][1] = f2tf32(a[(mr + 8) * SMS + ks + lk]);
                af[mt][2] = f2tf32(a[mr * SMS + ks + lk + 4]);
                af[mt][3] = f2tf32(a[(mr + 8) * SMS + ks + lk + 4]);
            }
#pragma unroll
            for (int nt = 0; nt < 4; nt++) {
                int nc = wn + nt * 8 + lr;
                bf[nt][0] = __float_as_uint(bp[nc * SMS + ks + lk]);
                bf[nt][1] = __float_as_uint(bp[nc * SMS + ks + lk + 4]);
            }
#pragma unroll
            for (int mt = 0; mt < 4; mt++)
#pragma unroll
                for (int nt = 0; nt < 4; nt++) {
                    asm volatile(
                        "mma.sync.aligned.m16n8k8.row.col.f32.tf32.tf32.f32 "
                        "{%0,%1,%2,%3}, {%4,%5,%6,%7}, {%8,%9}, {%0,%1,%2,%3};"
                        : "+f"(acc[mt][nt][0]), "+f"(acc[mt][nt][1]),
                          "+f"(acc[mt][nt][2]), "+f"(acc[mt][nt][3])
                        : "r"(af[mt][0]), "r"(af[mt][1]),
                          "r"(af[mt][2]), "r"(af[mt][3]),
                          "r"(bf[nt][0]), "r"(bf[nt][1]));
                }
        }
    };

    issue(0);
    if (nch > 1) issue(1);

    for (int c = 0; c < nch; c++) {
        asm volatile("cp.async.wait_group 1;" ::: "memory");
        __syncthreads();
        if (c + 2 < nch) issue(c + 2);
        compute(c);
        if (c + 1 < nch) __syncthreads();
    }

    // ---- epilogue ----
    const int cL = (lane & 3) * 2;
#pragma unroll
    for (int mt = 0; mt < 4; mt++) {
        int row = bm + wm + mt * 16 + lr;
#pragma unroll
        for (int nt = 0; nt < 4; nt++) {
            int col = bn + wn + nt * 8 + cL;
            float2 v0, v1;
            v0.x = acc[mt][nt][0] + bias[col];
            v0.y = acc[mt][nt][1] + bias[col + 1];
            v1.x = acc[mt][nt][2] + bias[col];
            v1.y = acc[mt][nt][3] + bias[col + 1];
            if (fuse == 1) {
                v0.x = fmaxf(v0.x, 0.f); v0.y = fmaxf(v0.y, 0.f);
                v1.x = fmaxf(v1.x, 0.f); v1.y = fmaxf(v1.y, 0.f);
            } else if (fuse == 2) {
                float2 r0v = *(const float2*)&res[(size_t)row * N + col];
                float2 r1v = *(const float2*)&res[(size_t)(row + 8) * N + col];
                v0.x += r0v.x; v0.y += r0v.y;
                v1.x += r1v.x; v1.y += r1v.y;
            }
            *(float2*)&C[(size_t)row * N + col] = v0;
            *(float2*)&C[(size_t)(row + 8) * N + col] = v1;
        }
    }
}

// ---------------------------------------------------------------------------
// q = src + pos
// ---------------------------------------------------------------------------
__global__ void add4_kernel(const float4* __restrict__ a,
                            const float4* __restrict__ b,
                            float4* __restrict__ c, int n4) {
    int i = blockIdx.x * blockDim.x + threadIdx.x;
    if (i < n4) {
        float4 x = a[i], y = b[i];
        x.x += y.x; x.y += y.y; x.z += y.z; x.w += y.w;
        c[i] = x;
    }
}

// ---------------------------------------------------------------------------
// Deformable sampling with FUSED softmax.
// One warp per (token, head); lane = channel (DH=32).
// oa layout per token (384): [0..255] offsets (h*32+..), [256..383] attn logits (h*16+..)
// ---------------------------------------------------------------------------
__global__ __launch_bounds__(256) void deform_sample_kernel(
    const float* __restrict__ value, const float* __restrict__ oa,
    const float* __restrict__ refp, float* __restrict__ out)
{
    const int lane = threadIdx.x & 31;
    const int wid  = blockIdx.x * (blockDim.x >> 5) + (threadIdx.x >> 5);
    const int tok = wid >> 3;
    const int h   = wid & 7;
    const int b   = tok / S_TOT;

    float offv  = oa[(size_t)tok * 384 + h * 32 + lane];
    float logit = (lane < 16) ? oa[(size_t)tok * 384 + 256 + h * 16 + lane] : -1e30f;
    float refv  = (lane < 8)  ? refp[(size_t)tok * 8 + lane] : 0.f;

    // softmax over 16 logits held in lanes 0..15 (xor<16 keeps groups separate)
    float m = logit;
#pragma unroll
    for (int o = 8; o > 0; o >>= 1) m = fmaxf(m, __shfl_xor_sync(0xffffffffu, m, o));
    float e = (lane < 16) ? expf(logit - m) : 0.f;
    float ssum = e;
#pragma unroll
    for (int o = 8; o > 0; o >>= 1) ssum += __shfl_xor_sync(0xffffffffu, ssum, o);
    float attnv = e / ssum;   // lanes>=16: garbage, never read

    const float* vbase = value + (size_t)b * S_TOT * 256 + h * 32 + lane;

    const int HW[4]     = {128, 64, 32, 16};
    const int starts[4] = {0, 16384, 20480, 21504};

    float acc = 0.f;
#pragma unroll
    for (int l = 0; l < 4; l++) {
        const int   Hl = HW[l], Wl = HW[l];
        const float fH = (float)Hl, fW = (float)Wl;
        float rx = __shfl_sync(0xffffffffu, refv, 2 * l);
        float ry = __shfl_sync(0xffffffffu, refv, 2 * l + 1);
        const float* vlev = vbase + (size_t)starts[l] * 256;
#pragma unroll
        for (int p = 0; p < 4; p++) {
            int j = l * 4 + p;
            float ox = __shfl_sync(0xffffffffu, offv, 2 * j);
            float oy = __shfl_sync(0xffffffffu, offv, 2 * j + 1);
            float aw = __shfl_sync(0xffffffffu, attnv, j);

            float locx = rx + ox / fW;
            float locy = ry + oy / fH;
            float x = locx * fW - 0.5f;
            float y = locy * fH - 0.5f;
            float x0f = floorf(x), y0f = floorf(y);
            float wx = x - x0f, wy = y - y0f;
            int x0 = (int)x0f, y0 = (int)y0f;

            bool vx0 = (x0 >= 0) && (x0 < Wl);
            bool vx1 = (x0 + 1 >= 0) && (x0 + 1 < Wl);
            bool vy0 = (y0 >= 0) && (y0 < Hl);
            bool vy1 = (y0 + 1 >= 0) && (y0 + 1 < Hl);

            float samp = 0.f;
            if (vy0) {
                const float* rowp = vlev + (size_t)(y0 * Wl) * 256;
                if (vx0) samp += (1.f - wx) * (1.f - wy) * rowp[(size_t)x0 * 256];
                if (vx1) samp += wx * (1.f - wy) * rowp[(size_t)(x0 + 1) * 256];
            }
            if (vy1) {
                const float* rowp = vlev + (size_t)((y0 + 1) * Wl) * 256;
                if (vx0) samp += (1.f - wx) * wy * rowp[(size_t)x0 * 256];
                if (vx1) samp += wx * wy * rowp[(size_t)(x0 + 1) * 256];
            }
            acc += aw * samp;
        }
    }
    out[(size_t)tok * 256 + h * 32 + lane] = acc;
}

// ---------------------------------------------------------------------------
// LayerNorm over D=256: one warp per row.
// ---------------------------------------------------------------------------
__global__ __launch_bounds__(256) void ln_kernel(
    const float* __restrict__ in, const float* __restrict__ gamma,
    const float* __restrict__ beta, float* __restrict__ out, int rows)
{
    const int lane = threadIdx.x & 31;
    const int row  = blockIdx.x * 8 + (threadIdx.x >> 5);
    if (row >= rows) return;
    const float* p = in + (size_t)row * 256;

    float v[8];
    float s = 0.f;
#pragma unroll
    for (int i = 0; i < 8; i++) { v[i] = p[i * 32 + lane]; s += v[i]; }
#pragma unroll
    for (int o = 16; o > 0; o >>= 1) s += __shfl_xor_sync(0xffffffffu, s, o);
    float mu = s * (1.f / 256.f);

    float vs = 0.f;
#pragma unroll
    for (int i = 0; i < 8; i++) { float d = v[i] - mu; vs += d * d; }
#pragma unroll
    for (int o = 16; o > 0; o >>= 1) vs += __shfl_xor_sync(0xffffffffu, vs, o);
    float rstd = rsqrtf(vs * (1.f / 256.f) + 1e-5f);

    float* q = out + (size_t)row * 256;
#pragma unroll
    for (int i = 0; i < 8; i++) {
        int c = i * 32 + lane;
        q[c] = (v[i] - mu) * rstd * gamma[c] + beta[c];
    }
}

// ---------------------------------------------------------------------------
// Launch
// ---------------------------------------------------------------------------
extern "C" void kernel_launch(void* const* d_in, const int* in_sizes, int n_in,
                              void* d_out, int out_size) {
    const float* src    = (const float*)d_in[0];
    const float* pos    = (const float*)d_in[1];
    const float* refp   = (const float*)d_in[2];
    const float* W_off  = (const float*)d_in[5];
    const float* b_off  = (const float*)d_in[6];
    const float* W_attn = (const float*)d_in[7];
    const float* b_attn = (const float*)d_in[8];
    const float* W_val  = (const float*)d_in[9];
    const float* b_val  = (const float*)d_in[10];
    const float* W_out  = (const float*)d_in[11];
    const float* b_out  = (const float*)d_in[12];
    const float* W_f1   = (const float*)d_in[13];
    const float* b_f1   = (const float*)d_in[14];
    const float* W_f2   = (const float*)d_in[15];
    const float* b_f2   = (const float*)d_in[16];
    const float* ln1g   = (const float*)d_in[17];
    const float* ln1b   = (const float*)d_in[18];
    const float* ln2g   = (const float*)d_in[19];
    const float* ln2b   = (const float*)d_in[20];
    float* out = (float*)d_out;

    float *q, *val, *oa, *acc, *y, *x, *ffn, *y2;
    float *wtv, *wtoa, *wtu, *wt1, *wt2, *boa;
    cudaGetSymbolAddress((void**)&q,    g_q);
    cudaGetSymbolAddress((void**)&val,  g_val);
    cudaGetSymbolAddress((void**)&oa,   g_oa);
    cudaGetSymbolAddress((void**)&acc,  g_acc);
    cudaGetSymbolAddress((void**)&y,    g_y);
    cudaGetSymbolAddress((void**)&x,    g_x);
    cudaGetSymbolAddress((void**)&ffn,  g_ffn);
    cudaGetSymbolAddress((void**)&y2,   g_y2);
    cudaGetSymbolAddress((void**)&wtv,  g_WT_val);
    cudaGetSymbolAddress((void**)&wtoa, g_WT_oa);
    cudaGetSymbolAddress((void**)&wtu,  g_WT_out);
    cudaGetSymbolAddress((void**)&wt1,  g_WT_f1);
    cudaGetSymbolAddress((void**)&wt2,  g_WT_f2);
    cudaGetSymbolAddress((void**)&boa,  g_b_oa);

    const int DYN = STG * BUF * 2 * 4;   // 61440 B
    static int attr_set = 0;
    cudaFuncSetAttribute(gemm_tc_kernel,
                         cudaFuncAttributeMaxDynamicSharedMemorySize, DYN);
    (void)attr_set;

    // 0. all weight transposes (tf32 pre-rounded) + bias concat, one launch
    transpose_all_kernel<<<738, dim3(32, 8)>>>(W_val, W_off, W_attn, W_out,
                                               W_f1, W_f2, b_off, b_attn);

    // 1. q = src + pos
    int n4 = M_TOK * DIM / 4;
    add4_kernel<<<(n4 + 255) / 256, 256>>>((const float4*)src, (const float4*)pos,
                                           (float4*)q, n4);

    dim3 grid256(DIM / 128, M_TOK / 128);   // (2, 340)
    dim3 gridOA(384 / 128, M_TOK / 128);    // (3, 340)
    dim3 gridFFN(DFF / 128, M_TOK / 128);   // (8, 340)

    // 2. value = src @ W_val + b_val
    gemm_tc_kernel<<<grid256, 256, DYN>>>(src, wtv, b_val, nullptr, val,
                                          M_TOK, DIM, DIM, 0);
    // 3. [off | attn logits] = q @ [W_off | W_attn] + [b_off | b_attn]
    gemm_tc_kernel<<<gridOA, 256, DYN>>>(q, wtoa, boa, nullptr, oa,
                                         M_TOK, 384, DIM, 0);
    // 4. deformable sampling (softmax fused) -> acc
    deform_sample_kernel<<<M_TOK * NHEAD / 8, 256>>>(val, oa, refp, acc);

    // 5. y = acc @ W_out + b_out + src
    gemm_tc_kernel<<<grid256, 256, DYN>>>(acc, wtu, b_out, src, y,
                                          M_TOK, DIM, DIM, 2);
    // 6. x = LN1(y)
    ln_kernel<<<M_TOK / 8, 256>>>(y, ln1g, ln1b, x, M_TOK);

    // 7. ffn = relu(x @ W_f1 + b_f1)
    gemm_tc_kernel<<<gridFFN, 256, DYN>>>(x, wt1, b_f1, nullptr, ffn,
                                          M_TOK, DFF, DIM, 1);
    // 8. y2 = ffn @ W_f2 + b_f2 + x
    gemm_tc_kernel<<<grid256, 256, DYN>>>(ffn, wt2, b_f2, x, y2,
                                          M_TOK, DIM, DFF, 2);
    // 9. out = LN2(y2)
    ln_kernel<<<M_TOK / 8, 256>>>(y2, ln2g, ln2b, out, M_TOK);
}